// round 4
// baseline (speedup 1.0000x reference)
#include <cuda_runtime.h>
#include <math.h>

// Problem constants (fixed by the dataset)
#define NV   100000
#define NE   600000
#define NF   200000
#define CINF 128
#define COUTF 128
#define HID  32

// ---------------- scratch (device globals; no allocation allowed) ----------
__device__ __align__(16) float g_nacc[NV * 3];        // raw accumulated face normals
__device__ int   g_deg[NV];
__device__ int   g_cursor[NV];
__device__ int   g_offs[NV + 1];
__device__ __align__(16) float g_x[(size_t)NV * CINF];   // features @ Wlin + blin  (51.2 MB)
__device__ int   g_csrc[NE];
__device__ float g_cw[NE];
__device__ float g_colsum[COUTF];
__device__ float g_colsq[COUTF];

// ---------------- f32x2 helpers (Blackwell packed fp32 FMA) ----------------
__device__ __forceinline__ unsigned long long pk2(float lo, float hi) {
    unsigned long long r;
    asm("mov.b64 %0, {%1, %2};" : "=l"(r) : "f"(lo), "f"(hi));
    return r;
}
__device__ __forceinline__ void ffma2(unsigned long long& acc,
                                      unsigned long long a,
                                      unsigned long long b) {
    asm("fma.rn.f32x2 %0, %1, %2, %0;" : "+l"(acc) : "l"(a), "l"(b));
}
__device__ __forceinline__ float2 upk2(unsigned long long v) {
    float2 f;
    asm("mov.b64 {%0, %1}, %2;" : "=f"(f.x), "=f"(f.y) : "l"(v));
    return f;
}

// ---------------- 0) zero-init scratch --------------------------------------
__global__ __launch_bounds__(256) void k_init() {
    int i = blockIdx.x * blockDim.x + threadIdx.x;
    if (i < NV * 3) g_nacc[i] = 0.f;
    if (i < NV) { g_deg[i] = 0; g_cursor[i] = 0; }
    if (i < COUTF) { g_colsum[i] = 0.f; g_colsq[i] = 0.f; }
}

// ---------------- 1) fused: face-normal scatter + in-degree count -----------
// threads [0, NF)            -> face normal accumulation
// threads [NF, NF+NE)        -> degree count of dst
__global__ __launch_bounds__(256) void k_scatter(const float* __restrict__ verts,
                                                 const int* __restrict__ faces,
                                                 const int* __restrict__ edges) {
    int i = blockIdx.x * blockDim.x + threadIdx.x;
    if (i < NF) {
        int f = i;
        int a = faces[f], b = faces[NF + f], c = faces[2 * NF + f];
        float ax = verts[3 * a], ay = verts[3 * a + 1], az = verts[3 * a + 2];
        float bx = verts[3 * b], by = verts[3 * b + 1], bz = verts[3 * b + 2];
        float cx = verts[3 * c], cy = verts[3 * c + 1], cz = verts[3 * c + 2];
        float e1x = bx - ax, e1y = by - ay, e1z = bz - az;
        float e2x = cx - ax, e2y = cy - ay, e2z = cz - az;
        float nx = e1y * e2z - e1z * e2y;
        float ny = e1z * e2x - e1x * e2z;
        float nz = e1x * e2y - e1y * e2x;
        atomicAdd(&g_nacc[3 * a], nx); atomicAdd(&g_nacc[3 * a + 1], ny); atomicAdd(&g_nacc[3 * a + 2], nz);
        atomicAdd(&g_nacc[3 * b], nx); atomicAdd(&g_nacc[3 * b + 1], ny); atomicAdd(&g_nacc[3 * b + 2], nz);
        atomicAdd(&g_nacc[3 * c], nx); atomicAdd(&g_nacc[3 * c + 1], ny); atomicAdd(&g_nacc[3 * c + 2], nz);
    } else if (i < NF + NE) {
        int e = i - NF;
        atomicAdd(&g_deg[edges[NE + e]], 1);
    }
}

// ---------------- 2) single-block exclusive scan (100k) ---------------------
__global__ __launch_bounds__(1024) void k_scan() {
    __shared__ int ssum[1024];
    const int CH = (NV + 1023) / 1024;  // 98
    int tid = threadIdx.x;
    int base = tid * CH;
    int local = 0;
    for (int i = 0; i < CH; i++) {
        int idx = base + i;
        if (idx < NV) local += g_deg[idx];
    }
    ssum[tid] = local;
    __syncthreads();
    for (int off = 1; off < 1024; off <<= 1) {
        int t = (tid >= off) ? ssum[tid - off] : 0;
        __syncthreads();
        ssum[tid] += t;
        __syncthreads();
    }
    int run = ssum[tid] - local;  // exclusive prefix for this chunk
    for (int i = 0; i < CH; i++) {
        int idx = base + i;
        if (idx < NV) { g_offs[idx] = run; run += g_deg[idx]; }
    }
    if (tid == 1023) g_offs[NV] = ssum[1023];
}

// ---------------- 3) per-edge metric MLP + CSR scatter -----------------------
// Source normal normalized here (identical math to reference:
// n_hat = n / (|n| + 1e-8)); removes a whole normalize pass/kernel.
__global__ __launch_bounds__(256) void k_edge(const float* __restrict__ verts,
                                              const int* __restrict__ edges,
                                              const float* __restrict__ W1,
                                              const float* __restrict__ b1,
                                              const float* __restrict__ W2,
                                              const float* __restrict__ b2) {
    __shared__ float sW1[3 * HID], sb1[HID], sW2[HID * 6], sb2[6];
    int t = threadIdx.x;
    if (t < 3 * HID) sW1[t] = W1[t];
    if (t < HID)     sb1[t] = b1[t];
    if (t < HID * 6) sW2[t] = W2[t];
    if (t < 6)       sb2[t] = b2[t];
    __syncthreads();

    int e = blockIdx.x * blockDim.x + t;
    if (e >= NE) return;
    int s = edges[e], d = edges[NE + e];
    float dx = verts[3 * d]     - verts[3 * s];
    float dy = verts[3 * d + 1] - verts[3 * s + 1];
    float dz = verts[3 * d + 2] - verts[3 * s + 2];
    float rnx = g_nacc[3 * s], rny = g_nacc[3 * s + 1], rnz = g_nacc[3 * s + 2];
    float inv = 1.f / (sqrtf(rnx * rnx + rny * rny + rnz * rnz) + 1e-8f);
    float nx = rnx * inv, ny = rny * inv, nz = rnz * inv;
    float dn = dx * nx + dy * ny + dz * nz;
    float tx = dx - dn * nx, ty = dy - dn * ny, tz = dz - dn * nz;

    float th0 = sb2[0], th1 = sb2[1], th2 = sb2[2], th3 = sb2[3], th4 = sb2[4], th5 = sb2[5];
#pragma unroll 8
    for (int j = 0; j < HID; j++) {
        float h = tx * sW1[j] + ty * sW1[HID + j] + tz * sW1[2 * HID + j] + sb1[j];
        h = fmaxf(h, 0.f);
        th0 += h * sW2[j * 6 + 0];
        th1 += h * sW2[j * 6 + 1];
        th2 += h * sW2[j * 6 + 2];
        th3 += h * sW2[j * 6 + 3];
        th4 += h * sW2[j * 6 + 4];
        th5 += h * sW2[j * 6 + 5];
    }
    // S = [[t0,t1,t2],[t1,t3,t4],[t2,t4,t5]];  q = t^T S S t = ||S t||^2
    float ux = th0 * tx + th1 * ty + th2 * tz;
    float uy = th1 * tx + th3 * ty + th4 * tz;
    float uz = th2 * tx + th4 * ty + th5 * tz;
    float q = ux * ux + uy * uy + uz * uz;
    float w = expf(-q);

    int pos = g_offs[d] + atomicAdd(&g_cursor[d], 1);
    g_csrc[pos] = s;
    g_cw[pos]  = w;
}

// ---------------- 4) x = features @ Wlin + blin  (FFMA2 SGEMM) ---------------
// 128-row x 128-col tile per block, 256 threads, 8x8 micro-tile, Ktile=32.
#define GEMM_MT 128
#define GEMM_KT 32
__global__ __launch_bounds__(256) void k_gemm(const float* __restrict__ A,
                                              const float* __restrict__ B,
                                              const float* __restrict__ bias) {
    __shared__ float As[GEMM_MT * 33];        // [row][k], padded row stride 33
    __shared__ float Bs[GEMM_KT * 128];       // [k][col]

    int tid = threadIdx.x;
    int tx = tid & 15;       // col group
    int ty = tid >> 4;       // row group
    int rowBase = blockIdx.x * GEMM_MT;

    unsigned long long acc[8][4];
#pragma unroll
    for (int r = 0; r < 8; r++)
#pragma unroll
        for (int g = 0; g < 4; g++) acc[r][g] = 0ull;

    for (int kt = 0; kt < CINF; kt += GEMM_KT) {
        // load A tile (coalesced: one warp per row, 32 k)
#pragma unroll
        for (int i = tid; i < GEMM_MT * GEMM_KT; i += 256) {
            int r = i >> 5, k = i & 31;
            int gr = rowBase + r;
            As[r * 33 + k] = (gr < NV) ? A[(size_t)gr * CINF + kt + k] : 0.f;
        }
        // load B tile (coalesced)
#pragma unroll
        for (int i = tid; i < GEMM_KT * 128; i += 256) {
            int k = i >> 7, c = i & 127;
            Bs[k * 128 + c] = B[(kt + k) * CINF + c];
        }
        __syncthreads();

#pragma unroll
        for (int k = 0; k < GEMM_KT; k++) {
            // b: cols [tx*4 .. +3] and [64+tx*4 .. +3] -> 256B-contiguous per phase
            float4 bA = *(const float4*)&Bs[k * 128 + tx * 4];
            float4 bB = *(const float4*)&Bs[k * 128 + 64 + tx * 4];
            unsigned long long bb0 = pk2(bA.x, bA.y);
            unsigned long long bb1 = pk2(bA.z, bA.w);
            unsigned long long bb2 = pk2(bB.x, bB.y);
            unsigned long long bb3 = pk2(bB.z, bB.w);
            float av[8];
#pragma unroll
            for (int r = 0; r < 8; r++) av[r] = As[(ty * 8 + r) * 33 + k];
#pragma unroll
            for (int r = 0; r < 8; r++) {
                unsigned long long ar = pk2(av[r], av[r]);
                ffma2(acc[r][0], ar, bb0);
                ffma2(acc[r][1], ar, bb1);
                ffma2(acc[r][2], ar, bb2);
                ffma2(acc[r][3], ar, bb3);
            }
        }
        __syncthreads();
    }

    float4 bi0 = ((const float4*)bias)[tx];
    float4 bi1 = ((const float4*)bias)[16 + tx];
#pragma unroll
    for (int r = 0; r < 8; r++) {
        int gr = rowBase + ty * 8 + r;
        if (gr >= NV) continue;
        float2 p0 = upk2(acc[r][0]), p1 = upk2(acc[r][1]);
        float2 p2 = upk2(acc[r][2]), p3 = upk2(acc[r][3]);
        float4 o0 = make_float4(p0.x + bi0.x, p0.y + bi0.y, p1.x + bi0.z, p1.y + bi0.w);
        float4 o1 = make_float4(p2.x + bi1.x, p2.y + bi1.y, p3.x + bi1.z, p3.y + bi1.w);
        *(float4*)&g_x[(size_t)gr * CINF + tx * 4] = o0;
        *(float4*)&g_x[(size_t)gr * CINF + 64 + tx * 4] = o1;
    }
}

// ---------------- 5) warp-per-vertex aggregation -----------------------------
__global__ __launch_bounds__(256) void k_agg(float* __restrict__ out) {
    int gw = (blockIdx.x * blockDim.x + threadIdx.x) >> 5;
    int lane = threadIdx.x & 31;
    if (gw >= NV) return;
    int s = g_offs[gw], e = g_offs[gw + 1];
    float4 acc = make_float4(0.f, 0.f, 0.f, 0.f);
    float den = 0.f;
    for (int i = s; i < e; i++) {
        float w = g_cw[i];          // uniform across warp: single broadcast request
        int sv = g_csrc[i];
        float4 xv = *(const float4*)&g_x[(size_t)sv * CINF + lane * 4];
        acc.x += w * xv.x; acc.y += w * xv.y; acc.z += w * xv.z; acc.w += w * xv.w;
        den += w;
    }
    float inv = 1.f / (den + 1e-5f);
    float4 o = make_float4(acc.x * inv, acc.y * inv, acc.z * inv, acc.w * inv);
    *(float4*)&out[(size_t)gw * COUTF + lane * 4] = o;
}

// ---------------- 6) per-column sum / sumsq ----------------------------------
// 800 CTAs x 125 rows: enough CTAs (>5 waves) to cover memory latency.
#define STAT_ROWS 125
__global__ __launch_bounds__(128) void k_stats(const float* __restrict__ out) {
    int col = threadIdx.x;            // 128 threads
    int r0 = blockIdx.x * STAT_ROWS;  // 800 blocks
    int r1 = r0 + STAT_ROWS;
    float s = 0.f, s2 = 0.f;
    for (int r = r0; r < r1; r++) {
        float v = out[(size_t)r * COUTF + col];
        s += v; s2 += v * v;
    }
    atomicAdd(&g_colsum[col], s);
    atomicAdd(&g_colsq[col], s2);
}

// ---------------- 7) normalize + ELU (in place) ------------------------------
__global__ __launch_bounds__(256) void k_final(float* __restrict__ out) {
    int i = blockIdx.x * blockDim.x + threadIdx.x;
    if (i >= NV * COUTF) return;
    int col = i & 127;
    float mu = g_colsum[col] * (1.f / NV);
    float var = (g_colsq[col] - (float)NV * mu * mu) * (1.f / (NV - 1));
    float sd = sqrtf(fmaxf(var, 0.f));
    float v = (out[i] - mu) / (sd + 1e-5f);
    out[i] = v > 0.f ? v : expm1f(v);
}

// ---------------- launcher ---------------------------------------------------
extern "C" void kernel_launch(void* const* d_in, const int* in_sizes, int n_in,
                              void* d_out, int out_size) {
    const float* features = (const float*)d_in[0];
    const float* vertices = (const float*)d_in[1];
    const int*   edges    = (const int*)  d_in[2];
    const int*   faces    = (const int*)  d_in[3];
    const float* W1       = (const float*)d_in[4];
    const float* b1       = (const float*)d_in[5];
    const float* W2       = (const float*)d_in[6];
    const float* b2       = (const float*)d_in[7];
    const float* Wlin     = (const float*)d_in[8];
    const float* blin     = (const float*)d_in[9];
    float* out = (float*)d_out;
    (void)in_sizes; (void)n_in; (void)out_size;

    k_init   <<<(NV * 3 + 255) / 256, 256>>>();
    k_scatter<<<(NF + NE + 255) / 256, 256>>>(vertices, faces, edges);
    k_scan   <<<1, 1024>>>();
    k_edge   <<<(NE + 255) / 256, 256>>>(vertices, edges, W1, b1, W2, b2);
    k_gemm   <<<(NV + GEMM_MT - 1) / GEMM_MT, 256>>>(features, Wlin, blin);
    k_agg    <<<(NV * 32 + 255) / 256, 256>>>(out);
    k_stats  <<<NV / STAT_ROWS, COUTF>>>(out);
    k_final  <<<(NV * COUTF + 255) / 256, 256>>>(out);
}

// round 9
// speedup vs baseline: 1.3695x; 1.3695x over previous
#include <cuda_runtime.h>
#include <math.h>

// Problem constants (fixed by the dataset)
#define NV   100000
#define NE   600000
#define NF   200000
#define CINF 128
#define COUTF 128
#define HID  32
#define SCAN_BLOCKS ((NV + 1023) / 1024)   // 98

// ---------------- scratch (device globals; no allocation allowed) ----------
__device__ __align__(16) float g_nacc[NV * 3];        // raw accumulated face normals
__device__ __align__(16) float4 g_pn[2 * NV];         // interleaved {pos, unit normal}
__device__ int   g_deg[NV];
__device__ int   g_cursor[NV];
__device__ int   g_offs[NV + 1];
__device__ int   g_bsum[128];
__device__ int   g_bpre[128];
__device__ __align__(16) float g_x[(size_t)NV * CINF];   // features @ Wlin + blin  (51.2 MB)
__device__ __align__(8) int2  g_adj[NE];              // {src, w bits}
__device__ float g_colsum[COUTF];
__device__ float g_colsq[COUTF];

// ---------------- f32x2 helpers (Blackwell packed fp32 FMA) ----------------
__device__ __forceinline__ unsigned long long pk2(float lo, float hi) {
    unsigned long long r;
    asm("mov.b64 %0, {%1, %2};" : "=l"(r) : "f"(lo), "f"(hi));
    return r;
}
__device__ __forceinline__ void ffma2(unsigned long long& acc,
                                      unsigned long long a,
                                      unsigned long long b) {
    asm("fma.rn.f32x2 %0, %1, %2, %0;" : "+l"(acc) : "l"(a), "l"(b));
}
__device__ __forceinline__ float2 upk2(unsigned long long v) {
    float2 f;
    asm("mov.b64 {%0, %1}, %2;" : "=f"(f.x), "=f"(f.y) : "l"(v));
    return f;
}

// ---------------- 0) zero-init scratch --------------------------------------
__global__ __launch_bounds__(256) void k_init() {
    int i = blockIdx.x * blockDim.x + threadIdx.x;
    if (i < NV * 3) g_nacc[i] = 0.f;
    if (i < NV) { g_deg[i] = 0; g_cursor[i] = 0; }
    if (i < COUTF) { g_colsum[i] = 0.f; g_colsq[i] = 0.f; }
}

// ---------------- 1) fused: face-normal scatter + in-degree count -----------
__global__ __launch_bounds__(256) void k_scatter(const float* __restrict__ verts,
                                                 const int* __restrict__ faces,
                                                 const int* __restrict__ edges) {
    int i = blockIdx.x * blockDim.x + threadIdx.x;
    if (i < NF) {
        int f = i;
        int a = faces[f], b = faces[NF + f], c = faces[2 * NF + f];
        float ax = verts[3 * a], ay = verts[3 * a + 1], az = verts[3 * a + 2];
        float bx = verts[3 * b], by = verts[3 * b + 1], bz = verts[3 * b + 2];
        float cx = verts[3 * c], cy = verts[3 * c + 1], cz = verts[3 * c + 2];
        float e1x = bx - ax, e1y = by - ay, e1z = bz - az;
        float e2x = cx - ax, e2y = cy - ay, e2z = cz - az;
        float nx = e1y * e2z - e1z * e2y;
        float ny = e1z * e2x - e1x * e2z;
        float nz = e1x * e2y - e1y * e2x;
        atomicAdd(&g_nacc[3 * a], nx); atomicAdd(&g_nacc[3 * a + 1], ny); atomicAdd(&g_nacc[3 * a + 2], nz);
        atomicAdd(&g_nacc[3 * b], nx); atomicAdd(&g_nacc[3 * b + 1], ny); atomicAdd(&g_nacc[3 * b + 2], nz);
        atomicAdd(&g_nacc[3 * c], nx); atomicAdd(&g_nacc[3 * c + 1], ny); atomicAdd(&g_nacc[3 * c + 2], nz);
    } else if (i < NF + NE) {
        int e = i - NF;
        atomicAdd(&g_deg[edges[NE + e]], 1);
    }
}

// ---------------- 2) parallel exclusive scan (3 phases, all coalesced) -------
// Phase A: per-block (1024 elems) exclusive scan via shfl + block total
__global__ __launch_bounds__(1024) void k_scanA() {
    __shared__ int wsum[32];
    int t = threadIdx.x, lane = t & 31, wid = t >> 5;
    int idx = blockIdx.x * 1024 + t;
    int v = (idx < NV) ? g_deg[idx] : 0;     // coalesced
    int x = v;
#pragma unroll
    for (int o = 1; o < 32; o <<= 1) {
        int y = __shfl_up_sync(0xffffffffu, x, o);
        if (lane >= o) x += y;
    }
    if (lane == 31) wsum[wid] = x;
    __syncthreads();
    if (wid == 0) {
        int s = wsum[lane];
#pragma unroll
        for (int o = 1; o < 32; o <<= 1) {
            int y = __shfl_up_sync(0xffffffffu, s, o);
            if (lane >= o) s += y;
        }
        wsum[lane] = s;
    }
    __syncthreads();
    int base = (wid > 0) ? wsum[wid - 1] : 0;
    if (idx < NV) g_offs[idx] = base + x - v;   // block-local exclusive, coalesced
    if (t == 1023) g_bsum[blockIdx.x] = base + x;  // block total
}

// Phase B: scan the 98 block totals (single tiny block)
__global__ __launch_bounds__(128) void k_scanB() {
    __shared__ int sh[128];
    int t = threadIdx.x;
    int v = (t < SCAN_BLOCKS) ? g_bsum[t] : 0;
    sh[t] = v;
    __syncthreads();
    for (int o = 1; o < 128; o <<= 1) {
        int y = (t >= o) ? sh[t - o] : 0;
        __syncthreads();
        sh[t] += y;
        __syncthreads();
    }
    if (t < SCAN_BLOCKS) g_bpre[t] = sh[t] - v;   // exclusive prefix per block
    if (t == 127) g_offs[NV] = sh[127];           // grand total (= NE)
}

// Phase C: add block prefixes (coalesced)
__global__ __launch_bounds__(1024) void k_scanC() {
    int idx = blockIdx.x * 1024 + threadIdx.x;
    if (idx < NV) g_offs[idx] += g_bpre[blockIdx.x];
}

// ---------------- 3) pack {pos, unit normal} per vertex ----------------------
// n_hat = n / (|n| + 1e-8), identical to reference math.
__global__ __launch_bounds__(256) void k_pack(const float* __restrict__ verts) {
    int v = blockIdx.x * blockDim.x + threadIdx.x;
    if (v >= NV) return;
    float px = verts[3 * v], py = verts[3 * v + 1], pz = verts[3 * v + 2];
    float nx = g_nacc[3 * v], ny = g_nacc[3 * v + 1], nz = g_nacc[3 * v + 2];
    float inv = 1.f / (sqrtf(nx * nx + ny * ny + nz * nz) + 1e-8f);
    g_pn[2 * v]     = make_float4(px, py, pz, 0.f);
    g_pn[2 * v + 1] = make_float4(nx * inv, ny * inv, nz * inv, 0.f);
}

// ---------------- 4) per-edge metric MLP + CSR scatter -----------------------
// 3 float4 gathers per edge (vs 9 scalar gathers) — l1tex wavefront count /3.
__global__ __launch_bounds__(256) void k_edge(const int* __restrict__ edges,
                                              const float* __restrict__ W1,
                                              const float* __restrict__ b1,
                                              const float* __restrict__ W2,
                                              const float* __restrict__ b2) {
    __shared__ float sW1[3 * HID], sb1[HID], sW2[HID * 6], sb2[6];
    int t = threadIdx.x;
    if (t < 3 * HID) sW1[t] = W1[t];
    if (t < HID)     sb1[t] = b1[t];
    if (t < HID * 6) sW2[t] = W2[t];
    if (t < 6)       sb2[t] = b2[t];
    __syncthreads();

    int e = blockIdx.x * blockDim.x + t;
    if (e >= NE) return;
    int s = edges[e], d = edges[NE + e];
    float4 ps = g_pn[2 * s];
    float4 ns = g_pn[2 * s + 1];
    float4 pd = g_pn[2 * d];
    float dx = pd.x - ps.x, dy = pd.y - ps.y, dz = pd.z - ps.z;
    float dn = dx * ns.x + dy * ns.y + dz * ns.z;
    float tx = dx - dn * ns.x, ty = dy - dn * ns.y, tz = dz - dn * ns.z;

    float th0 = sb2[0], th1 = sb2[1], th2 = sb2[2], th3 = sb2[3], th4 = sb2[4], th5 = sb2[5];
#pragma unroll 8
    for (int j = 0; j < HID; j++) {
        float h = tx * sW1[j] + ty * sW1[HID + j] + tz * sW1[2 * HID + j] + sb1[j];
        h = fmaxf(h, 0.f);
        th0 += h * sW2[j * 6 + 0];
        th1 += h * sW2[j * 6 + 1];
        th2 += h * sW2[j * 6 + 2];
        th3 += h * sW2[j * 6 + 3];
        th4 += h * sW2[j * 6 + 4];
        th5 += h * sW2[j * 6 + 5];
    }
    // S = [[t0,t1,t2],[t1,t3,t4],[t2,t4,t5]];  q = t^T S S t = ||S t||^2
    float ux = th0 * tx + th1 * ty + th2 * tz;
    float uy = th1 * tx + th3 * ty + th4 * tz;
    float uz = th2 * tx + th4 * ty + th5 * tz;
    float q = ux * ux + uy * uy + uz * uz;
    float w = expf(-q);

    int pos = g_offs[d] + atomicAdd(&g_cursor[d], 1);
    g_adj[pos] = make_int2(s, __float_as_int(w));
}

// ---------------- 5) x = features @ Wlin + blin  (FFMA2 SGEMM) ---------------
#define GEMM_MT 128
#define GEMM_KT 32
__global__ __launch_bounds__(256) void k_gemm(const float* __restrict__ A,
                                              const float* __restrict__ B,
                                              const float* __restrict__ bias) {
    __shared__ float As[GEMM_MT * 33];        // [row][k], padded row stride 33
    __shared__ float Bs[GEMM_KT * 128];       // [k][col]

    int tid = threadIdx.x;
    int tx = tid & 15;       // col group
    int ty = tid >> 4;       // row group
    int rowBase = blockIdx.x * GEMM_MT;

    unsigned long long acc[8][4];
#pragma unroll
    for (int r = 0; r < 8; r++)
#pragma unroll
        for (int g = 0; g < 4; g++) acc[r][g] = 0ull;

    for (int kt = 0; kt < CINF; kt += GEMM_KT) {
#pragma unroll
        for (int i = tid; i < GEMM_MT * GEMM_KT; i += 256) {
            int r = i >> 5, k = i & 31;
            int gr = rowBase + r;
            As[r * 33 + k] = (gr < NV) ? A[(size_t)gr * CINF + kt + k] : 0.f;
        }
#pragma unroll
        for (int i = tid; i < GEMM_KT * 128; i += 256) {
            int k = i >> 7, c = i & 127;
            Bs[k * 128 + c] = B[(kt + k) * CINF + c];
        }
        __syncthreads();

#pragma unroll
        for (int k = 0; k < GEMM_KT; k++) {
            float4 bA = *(const float4*)&Bs[k * 128 + tx * 4];
            float4 bB = *(const float4*)&Bs[k * 128 + 64 + tx * 4];
            unsigned long long bb0 = pk2(bA.x, bA.y);
            unsigned long long bb1 = pk2(bA.z, bA.w);
            unsigned long long bb2 = pk2(bB.x, bB.y);
            unsigned long long bb3 = pk2(bB.z, bB.w);
            float av[8];
#pragma unroll
            for (int r = 0; r < 8; r++) av[r] = As[(ty * 8 + r) * 33 + k];
#pragma unroll
            for (int r = 0; r < 8; r++) {
                unsigned long long ar = pk2(av[r], av[r]);
                ffma2(acc[r][0], ar, bb0);
                ffma2(acc[r][1], ar, bb1);
                ffma2(acc[r][2], ar, bb2);
                ffma2(acc[r][3], ar, bb3);
            }
        }
        __syncthreads();
    }

    float4 bi0 = ((const float4*)bias)[tx];
    float4 bi1 = ((const float4*)bias)[16 + tx];
#pragma unroll
    for (int r = 0; r < 8; r++) {
        int gr = rowBase + ty * 8 + r;
        if (gr >= NV) continue;
        float2 p0 = upk2(acc[r][0]), p1 = upk2(acc[r][1]);
        float2 p2 = upk2(acc[r][2]), p3 = upk2(acc[r][3]);
        float4 o0 = make_float4(p0.x + bi0.x, p0.y + bi0.y, p1.x + bi0.z, p1.y + bi0.w);
        float4 o1 = make_float4(p2.x + bi1.x, p2.y + bi1.y, p3.x + bi1.z, p3.y + bi1.w);
        *(float4*)&g_x[(size_t)gr * CINF + tx * 4] = o0;
        *(float4*)&g_x[(size_t)gr * CINF + 64 + tx * 4] = o1;
    }
}

// ---------------- 6) warp-per-vertex aggregation (2x unrolled, dual acc) -----
__global__ __launch_bounds__(256) void k_agg(float* __restrict__ out) {
    int gw = (blockIdx.x * blockDim.x + threadIdx.x) >> 5;
    int lane = threadIdx.x & 31;
    if (gw >= NV) return;
    int s = g_offs[gw], e = g_offs[gw + 1];
    float4 acc0 = make_float4(0.f, 0.f, 0.f, 0.f);
    float4 acc1 = make_float4(0.f, 0.f, 0.f, 0.f);
    float den = 0.f;
    int i = s;
    for (; i + 1 < e; i += 2) {
        int2 a0 = __ldg(&g_adj[i]);      // both broadcasts issued before gathers
        int2 a1 = __ldg(&g_adj[i + 1]);  // -> 2 outstanding float4 gathers (MLP=2)
        float w0 = __int_as_float(a0.y);
        float w1 = __int_as_float(a1.y);
        float4 x0 = *(const float4*)&g_x[(size_t)a0.x * CINF + lane * 4];
        float4 x1 = *(const float4*)&g_x[(size_t)a1.x * CINF + lane * 4];
        acc0.x += w0 * x0.x; acc0.y += w0 * x0.y; acc0.z += w0 * x0.z; acc0.w += w0 * x0.w;
        acc1.x += w1 * x1.x; acc1.y += w1 * x1.y; acc1.z += w1 * x1.z; acc1.w += w1 * x1.w;
        den += w0 + w1;
    }
    if (i < e) {
        int2 a = __ldg(&g_adj[i]);
        float w = __int_as_float(a.y);
        float4 xv = *(const float4*)&g_x[(size_t)a.x * CINF + lane * 4];
        acc0.x += w * xv.x; acc0.y += w * xv.y; acc0.z += w * xv.z; acc0.w += w * xv.w;
        den += w;
    }
    float inv = 1.f / (den + 1e-5f);
    float4 o = make_float4((acc0.x + acc1.x) * inv, (acc0.y + acc1.y) * inv,
                           (acc0.z + acc1.z) * inv, (acc0.w + acc1.w) * inv);
    *(float4*)&out[(size_t)gw * COUTF + lane * 4] = o;
}

// ---------------- 7) per-column sum / sumsq ----------------------------------
#define STAT_ROWS 125
__global__ __launch_bounds__(128) void k_stats(const float* __restrict__ out) {
    int col = threadIdx.x;            // 128 threads
    int r0 = blockIdx.x * STAT_ROWS;  // 800 blocks
    int r1 = r0 + STAT_ROWS;
    float s = 0.f, s2 = 0.f;
    for (int r = r0; r < r1; r++) {
        float v = out[(size_t)r * COUTF + col];
        s += v; s2 += v * v;
    }
    atomicAdd(&g_colsum[col], s);
    atomicAdd(&g_colsq[col], s2);
}

// ---------------- 8) normalize + ELU (in place) ------------------------------
__global__ __launch_bounds__(256) void k_final(float* __restrict__ out) {
    int i = blockIdx.x * blockDim.x + threadIdx.x;
    if (i >= NV * COUTF) return;
    int col = i & 127;
    float mu = g_colsum[col] * (1.f / NV);
    float var = (g_colsq[col] - (float)NV * mu * mu) * (1.f / (NV - 1));
    float sd = sqrtf(fmaxf(var, 0.f));
    float v = (out[i] - mu) / (sd + 1e-5f);
    out[i] = v > 0.f ? v : expm1f(v);
}

// ---------------- launcher ---------------------------------------------------
extern "C" void kernel_launch(void* const* d_in, const int* in_sizes, int n_in,
                              void* d_out, int out_size) {
    const float* features = (const float*)d_in[0];
    const float* vertices = (const float*)d_in[1];
    const int*   edges    = (const int*)  d_in[2];
    const int*   faces    = (const int*)  d_in[3];
    const float* W1       = (const float*)d_in[4];
    const float* b1       = (const float*)d_in[5];
    const float* W2       = (const float*)d_in[6];
    const float* b2       = (const float*)d_in[7];
    const float* Wlin     = (const float*)d_in[8];
    const float* blin     = (const float*)d_in[9];
    float* out = (float*)d_out;
    (void)in_sizes; (void)n_in; (void)out_size;

    k_init   <<<(NV * 3 + 255) / 256, 256>>>();
    k_scatter<<<(NF + NE + 255) / 256, 256>>>(vertices, faces, edges);
    k_scanA  <<<SCAN_BLOCKS, 1024>>>();
    k_scanB  <<<1, 128>>>();
    k_scanC  <<<SCAN_BLOCKS, 1024>>>();
    k_gemm   <<<(NV + GEMM_MT - 1) / GEMM_MT, 256>>>(features, Wlin, blin);
    k_pack   <<<(NV + 255) / 256, 256>>>(vertices);
    k_edge   <<<(NE + 255) / 256, 256>>>(edges, W1, b1, W2, b2);
    k_agg    <<<(NV * 32 + 255) / 256, 256>>>(out);
    k_stats  <<<NV / STAT_ROWS, COUTF>>>(out);
    k_final  <<<(NV * COUTF + 255) / 256, 256>>>(out);
}

// round 14
// speedup vs baseline: 1.4189x; 1.0361x over previous
#include <cuda_runtime.h>
#include <math.h>

// Problem constants (fixed by the dataset)
#define NV   100000
#define NE   600000
#define NF   200000
#define CINF 128
#define COUTF 128
#define HID  32
#define SCAN_BLOCKS ((NV + 1023) / 1024)   // 98

// ---------------- scratch (device globals; no allocation allowed) ----------
__device__ __align__(16) float g_nacc[NV * 3];        // raw accumulated face normals
__device__ __align__(16) float4 g_pn[2 * NV];         // interleaved {pos, unit normal}
__device__ int   g_deg[NV];
__device__ int   g_cursor[NV];
__device__ int   g_offs[NV + 1];
__device__ int   g_bsum[128];
__device__ int   g_bpre[128];
__device__ __align__(16) float g_x[(size_t)NV * CINF];   // features @ Wlin + blin  (51.2 MB)
__device__ __align__(8) int2  g_adj[NE];              // {src, w bits}
__device__ float g_colsum[COUTF];
__device__ float g_colsq[COUTF];

// ---------------- f32x2 helpers (Blackwell packed fp32 FMA) ----------------
__device__ __forceinline__ unsigned long long pk2(float lo, float hi) {
    unsigned long long r;
    asm("mov.b64 %0, {%1, %2};" : "=l"(r) : "f"(lo), "f"(hi));
    return r;
}
__device__ __forceinline__ void ffma2(unsigned long long& acc,
                                      unsigned long long a,
                                      unsigned long long b) {
    asm("fma.rn.f32x2 %0, %1, %2, %0;" : "+l"(acc) : "l"(a), "l"(b));
}
__device__ __forceinline__ float2 upk2(unsigned long long v) {
    float2 f;
    asm("mov.b64 {%0, %1}, %2;" : "=f"(f.x), "=f"(f.y) : "l"(v));
    return f;
}

// ---------------- 0) zero-init scratch --------------------------------------
__global__ __launch_bounds__(256) void k_init() {
    int i = blockIdx.x * blockDim.x + threadIdx.x;
    if (i < NV * 3) g_nacc[i] = 0.f;
    if (i < NV) { g_deg[i] = 0; g_cursor[i] = 0; }
    if (i < COUTF) { g_colsum[i] = 0.f; g_colsq[i] = 0.f; }
}

// ---------------- 1) fused: face-normal scatter + in-degree count -----------
__global__ __launch_bounds__(256) void k_scatter(const float* __restrict__ verts,
                                                 const int* __restrict__ faces,
                                                 const int* __restrict__ edges) {
    int i = blockIdx.x * blockDim.x + threadIdx.x;
    if (i < NF) {
        int f = i;
        int a = faces[f], b = faces[NF + f], c = faces[2 * NF + f];
        float ax = verts[3 * a], ay = verts[3 * a + 1], az = verts[3 * a + 2];
        float bx = verts[3 * b], by = verts[3 * b + 1], bz = verts[3 * b + 2];
        float cx = verts[3 * c], cy = verts[3 * c + 1], cz = verts[3 * c + 2];
        float e1x = bx - ax, e1y = by - ay, e1z = bz - az;
        float e2x = cx - ax, e2y = cy - ay, e2z = cz - az;
        float nx = e1y * e2z - e1z * e2y;
        float ny = e1z * e2x - e1x * e2z;
        float nz = e1x * e2y - e1y * e2x;
        atomicAdd(&g_nacc[3 * a], nx); atomicAdd(&g_nacc[3 * a + 1], ny); atomicAdd(&g_nacc[3 * a + 2], nz);
        atomicAdd(&g_nacc[3 * b], nx); atomicAdd(&g_nacc[3 * b + 1], ny); atomicAdd(&g_nacc[3 * b + 2], nz);
        atomicAdd(&g_nacc[3 * c], nx); atomicAdd(&g_nacc[3 * c + 1], ny); atomicAdd(&g_nacc[3 * c + 2], nz);
    } else if (i < NF + NE) {
        int e = i - NF;
        atomicAdd(&g_deg[edges[NE + e]], 1);
    }
}

// ---------------- 2) parallel exclusive scan (3 phases, all coalesced) -------
// Phase A: per-block (1024 elems) exclusive scan via shfl + block total
__global__ __launch_bounds__(1024) void k_scanA() {
    __shared__ int wsum[32];
    int t = threadIdx.x, lane = t & 31, wid = t >> 5;
    int idx = blockIdx.x * 1024 + t;
    int v = (idx < NV) ? g_deg[idx] : 0;     // coalesced
    int x = v;
#pragma unroll
    for (int o = 1; o < 32; o <<= 1) {
        int y = __shfl_up_sync(0xffffffffu, x, o);
        if (lane >= o) x += y;
    }
    if (lane == 31) wsum[wid] = x;
    __syncthreads();
    if (wid == 0) {
        int s = wsum[lane];
#pragma unroll
        for (int o = 1; o < 32; o <<= 1) {
            int y = __shfl_up_sync(0xffffffffu, s, o);
            if (lane >= o) s += y;
        }
        wsum[lane] = s;
    }
    __syncthreads();
    int base = (wid > 0) ? wsum[wid - 1] : 0;
    if (idx < NV) g_offs[idx] = base + x - v;   // block-local exclusive, coalesced
    if (t == 1023) g_bsum[blockIdx.x] = base + x;  // block total
}

// Phase B: scan the 98 block totals (single tiny block)
__global__ __launch_bounds__(128) void k_scanB() {
    __shared__ int sh[128];
    int t = threadIdx.x;
    int v = (t < SCAN_BLOCKS) ? g_bsum[t] : 0;
    sh[t] = v;
    __syncthreads();
    for (int o = 1; o < 128; o <<= 1) {
        int y = (t >= o) ? sh[t - o] : 0;
        __syncthreads();
        sh[t] += y;
        __syncthreads();
    }
    if (t < SCAN_BLOCKS) g_bpre[t] = sh[t] - v;   // exclusive prefix per block
    if (t == 127) g_offs[NV] = sh[127];           // grand total (= NE)
}

// Phase C: add block prefixes (coalesced) + FUSED per-vertex pack
// n_hat = n / (|n| + 1e-8), identical to reference math.
__global__ __launch_bounds__(1024) void k_scanC(const float* __restrict__ verts) {
    int idx = blockIdx.x * 1024 + threadIdx.x;
    if (idx >= NV) return;
    g_offs[idx] += g_bpre[blockIdx.x];
    float px = verts[3 * idx], py = verts[3 * idx + 1], pz = verts[3 * idx + 2];
    float nx = g_nacc[3 * idx], ny = g_nacc[3 * idx + 1], nz = g_nacc[3 * idx + 2];
    float inv = 1.f / (sqrtf(nx * nx + ny * ny + nz * nz) + 1e-8f);
    g_pn[2 * idx]     = make_float4(px, py, pz, 0.f);
    g_pn[2 * idx + 1] = make_float4(nx * inv, ny * inv, nz * inv, 0.f);
}

// ---------------- 3) per-edge metric MLP + CSR scatter -----------------------
// 3 float4 gathers per edge (vs 9 scalar gathers) — l1tex wavefront count /3.
__global__ __launch_bounds__(256) void k_edge(const int* __restrict__ edges,
                                              const float* __restrict__ W1,
                                              const float* __restrict__ b1,
                                              const float* __restrict__ W2,
                                              const float* __restrict__ b2) {
    __shared__ float sW1[3 * HID], sb1[HID], sW2[HID * 6], sb2[6];
    int t = threadIdx.x;
    if (t < 3 * HID) sW1[t] = W1[t];
    if (t < HID)     sb1[t] = b1[t];
    if (t < HID * 6) sW2[t] = W2[t];
    if (t < 6)       sb2[t] = b2[t];
    __syncthreads();

    int e = blockIdx.x * blockDim.x + t;
    if (e >= NE) return;
    int s = edges[e], d = edges[NE + e];
    float4 ps = g_pn[2 * s];
    float4 ns = g_pn[2 * s + 1];
    float4 pd = g_pn[2 * d];
    float dx = pd.x - ps.x, dy = pd.y - ps.y, dz = pd.z - ps.z;
    float dn = dx * ns.x + dy * ns.y + dz * ns.z;
    float tx = dx - dn * ns.x, ty = dy - dn * ns.y, tz = dz - dn * ns.z;

    float th0 = sb2[0], th1 = sb2[1], th2 = sb2[2], th3 = sb2[3], th4 = sb2[4], th5 = sb2[5];
#pragma unroll 8
    for (int j = 0; j < HID; j++) {
        float h = tx * sW1[j] + ty * sW1[HID + j] + tz * sW1[2 * HID + j] + sb1[j];
        h = fmaxf(h, 0.f);
        th0 += h * sW2[j * 6 + 0];
        th1 += h * sW2[j * 6 + 1];
        th2 += h * sW2[j * 6 + 2];
        th3 += h * sW2[j * 6 + 3];
        th4 += h * sW2[j * 6 + 4];
        th5 += h * sW2[j * 6 + 5];
    }
    // S = [[t0,t1,t2],[t1,t3,t4],[t2,t4,t5]];  q = t^T S S t = ||S t||^2
    float ux = th0 * tx + th1 * ty + th2 * tz;
    float uy = th1 * tx + th3 * ty + th4 * tz;
    float uz = th2 * tx + th4 * ty + th5 * tz;
    float q = ux * ux + uy * uy + uz * uz;
    float w = expf(-q);

    int pos = g_offs[d] + atomicAdd(&g_cursor[d], 1);
    g_adj[pos] = make_int2(s, __float_as_int(w));
}

// ---------------- 4) x = features @ Wlin + blin  (FFMA2 SGEMM) ---------------
#define GEMM_MT 128
#define GEMM_KT 32
__global__ __launch_bounds__(256) void k_gemm(const float* __restrict__ A,
                                              const float* __restrict__ B,
                                              const float* __restrict__ bias) {
    __shared__ float As[GEMM_MT * 33];        // [row][k], padded row stride 33
    __shared__ float Bs[GEMM_KT * 128];       // [k][col]

    int tid = threadIdx.x;
    int tx = tid & 15;       // col group
    int ty = tid >> 4;       // row group
    int rowBase = blockIdx.x * GEMM_MT;

    unsigned long long acc[8][4];
#pragma unroll
    for (int r = 0; r < 8; r++)
#pragma unroll
        for (int g = 0; g < 4; g++) acc[r][g] = 0ull;

    for (int kt = 0; kt < CINF; kt += GEMM_KT) {
#pragma unroll
        for (int i = tid; i < GEMM_MT * GEMM_KT; i += 256) {
            int r = i >> 5, k = i & 31;
            int gr = rowBase + r;
            As[r * 33 + k] = (gr < NV) ? A[(size_t)gr * CINF + kt + k] : 0.f;
        }
#pragma unroll
        for (int i = tid; i < GEMM_KT * 128; i += 256) {
            int k = i >> 7, c = i & 127;
            Bs[k * 128 + c] = B[(kt + k) * CINF + c];
        }
        __syncthreads();

#pragma unroll
        for (int k = 0; k < GEMM_KT; k++) {
            float4 bA = *(const float4*)&Bs[k * 128 + tx * 4];
            float4 bB = *(const float4*)&Bs[k * 128 + 64 + tx * 4];
            unsigned long long bb0 = pk2(bA.x, bA.y);
            unsigned long long bb1 = pk2(bA.z, bA.w);
            unsigned long long bb2 = pk2(bB.x, bB.y);
            unsigned long long bb3 = pk2(bB.z, bB.w);
            float av[8];
#pragma unroll
            for (int r = 0; r < 8; r++) av[r] = As[(ty * 8 + r) * 33 + k];
#pragma unroll
            for (int r = 0; r < 8; r++) {
                unsigned long long ar = pk2(av[r], av[r]);
                ffma2(acc[r][0], ar, bb0);
                ffma2(acc[r][1], ar, bb1);
                ffma2(acc[r][2], ar, bb2);
                ffma2(acc[r][3], ar, bb3);
            }
        }
        __syncthreads();
    }

    float4 bi0 = ((const float4*)bias)[tx];
    float4 bi1 = ((const float4*)bias)[16 + tx];
#pragma unroll
    for (int r = 0; r < 8; r++) {
        int gr = rowBase + ty * 8 + r;
        if (gr >= NV) continue;
        float2 p0 = upk2(acc[r][0]), p1 = upk2(acc[r][1]);
        float2 p2 = upk2(acc[r][2]), p3 = upk2(acc[r][3]);
        float4 o0 = make_float4(p0.x + bi0.x, p0.y + bi0.y, p1.x + bi0.z, p1.y + bi0.w);
        float4 o1 = make_float4(p2.x + bi1.x, p2.y + bi1.y, p3.x + bi1.z, p3.y + bi1.w);
        *(float4*)&g_x[(size_t)gr * CINF + tx * 4] = o0;
        *(float4*)&g_x[(size_t)gr * CINF + 64 + tx * 4] = o1;
    }
}

// ---------------- 5) warp-per-vertex aggregation (2x unrolled, dual acc) -----
__global__ __launch_bounds__(256) void k_agg(float* __restrict__ out) {
    int gw = (blockIdx.x * blockDim.x + threadIdx.x) >> 5;
    int lane = threadIdx.x & 31;
    if (gw >= NV) return;
    int s = g_offs[gw], e = g_offs[gw + 1];
    float4 acc0 = make_float4(0.f, 0.f, 0.f, 0.f);
    float4 acc1 = make_float4(0.f, 0.f, 0.f, 0.f);
    float den = 0.f;
    int i = s;
    for (; i + 1 < e; i += 2) {
        int2 a0 = __ldg(&g_adj[i]);      // both broadcasts issued before gathers
        int2 a1 = __ldg(&g_adj[i + 1]);  // -> 2 outstanding float4 gathers (MLP=2)
        float w0 = __int_as_float(a0.y);
        float w1 = __int_as_float(a1.y);
        float4 x0 = *(const float4*)&g_x[(size_t)a0.x * CINF + lane * 4];
        float4 x1 = *(const float4*)&g_x[(size_t)a1.x * CINF + lane * 4];
        acc0.x += w0 * x0.x; acc0.y += w0 * x0.y; acc0.z += w0 * x0.z; acc0.w += w0 * x0.w;
        acc1.x += w1 * x1.x; acc1.y += w1 * x1.y; acc1.z += w1 * x1.z; acc1.w += w1 * x1.w;
        den += w0 + w1;
    }
    if (i < e) {
        int2 a = __ldg(&g_adj[i]);
        float w = __int_as_float(a.y);
        float4 xv = *(const float4*)&g_x[(size_t)a.x * CINF + lane * 4];
        acc0.x += w * xv.x; acc0.y += w * xv.y; acc0.z += w * xv.z; acc0.w += w * xv.w;
        den += w;
    }
    float inv = 1.f / (den + 1e-5f);
    float4 o = make_float4((acc0.x + acc1.x) * inv, (acc0.y + acc1.y) * inv,
                           (acc0.z + acc1.z) * inv, (acc0.w + acc1.w) * inv);
    *(float4*)&out[(size_t)gw * COUTF + lane * 4] = o;
}

// ---------------- 6) per-column sum / sumsq ----------------------------------
#define STAT_ROWS 125
__global__ __launch_bounds__(128) void k_stats(const float* __restrict__ out) {
    int col = threadIdx.x;            // 128 threads
    int r0 = blockIdx.x * STAT_ROWS;  // 800 blocks
    int r1 = r0 + STAT_ROWS;
    float s = 0.f, s2 = 0.f;
    for (int r = r0; r < r1; r++) {
        float v = out[(size_t)r * COUTF + col];
        s += v; s2 += v * v;
    }
    atomicAdd(&g_colsum[col], s);
    atomicAdd(&g_colsq[col], s2);
}

// ---------------- 7) normalize + ELU (in place, float4-vectorized) -----------
__global__ __launch_bounds__(256) void k_final(float* __restrict__ out) {
    int q = blockIdx.x * blockDim.x + threadIdx.x;   // one float4 per thread
    if (q >= NV * COUTF / 4) return;
    int colq = (q & 31) * 4;                          // column of .x (row-major, COUTF=128)
    float4 v = *(float4*)&out[(size_t)q * 4];
    const float rn = 1.f / NV, rn1 = 1.f / (NV - 1);
#pragma unroll
    for (int j = 0; j < 4; j++) {
        float* pv = (j == 0) ? &v.x : (j == 1) ? &v.y : (j == 2) ? &v.z : &v.w;
        int col = colq + j;
        float mu = g_colsum[col] * rn;
        float var = (g_colsq[col] - (float)NV * mu * mu) * rn1;
        float sd = sqrtf(fmaxf(var, 0.f));
        float t = (*pv - mu) / (sd + 1e-5f);
        *pv = t > 0.f ? t : expm1f(t);
    }
    *(float4*)&out[(size_t)q * 4] = v;
}

// ---------------- launcher ---------------------------------------------------
extern "C" void kernel_launch(void* const* d_in, const int* in_sizes, int n_in,
                              void* d_out, int out_size) {
    const float* features = (const float*)d_in[0];
    const float* vertices = (const float*)d_in[1];
    const int*   edges    = (const int*)  d_in[2];
    const int*   faces    = (const int*)  d_in[3];
    const float* W1       = (const float*)d_in[4];
    const float* b1       = (const float*)d_in[5];
    const float* W2       = (const float*)d_in[6];
    const float* b2       = (const float*)d_in[7];
    const float* Wlin     = (const float*)d_in[8];
    const float* blin     = (const float*)d_in[9];
    float* out = (float*)d_out;
    (void)in_sizes; (void)n_in; (void)out_size;

    // k_gemm is launch #4 — the slot ncu's -s/-c capture lands on (empirical:
    // R4 captured 4th launch k_edge, R9 captured 4th launch k_scanB).
    k_init   <<<(NV * 3 + 255) / 256, 256>>>();
    k_scatter<<<(NF + NE + 255) / 256, 256>>>(vertices, faces, edges);
    k_scanA  <<<SCAN_BLOCKS, 1024>>>();
    k_gemm   <<<(NV + GEMM_MT - 1) / GEMM_MT, 256>>>(features, Wlin, blin);
    k_scanB  <<<1, 128>>>();
    k_scanC  <<<SCAN_BLOCKS, 1024>>>(vertices);
    k_edge   <<<(NE + 255) / 256, 256>>>(edges, W1, b1, W2, b2);
    k_agg    <<<(NV * 32 + 255) / 256, 256>>>(out);
    k_stats  <<<NV / STAT_ROWS, COUTF>>>(out);
    k_final  <<<(NV * COUTF / 4 + 255) / 256, 256>>>(out);
}